// round 9
// baseline (speedup 1.0000x reference)
#include <cuda_runtime.h>
#include <math.h>

#define NN 3072
#define DIN 512
#define NH 16
#define HDIM 64
#define HDT 1024
#define SMP 68

// ---------------- scratch (device globals; no allocations allowed) ----------
__device__ float g_Q[NH * NN * HDIM];     // [h][n][d]
__device__ float g_K[NH * NN * HDIM];
__device__ float g_V[NH * NN * HDIM];
__device__ float g_Bm[(size_t)NN * NN];   // masked bias
__device__ float g_vals[NN * HDT];        // attention output [n][h*64+d]
__device__ float g_o1[NN * HDT];          // after first o_proj layer + mish

// ---------------- prep: masked bias + bias passthrough ----------------------
__global__ void __launch_bounds__(256) prep_kernel(
    const float4* __restrict__ bias, const int4* __restrict__ mask,
    float4* __restrict__ out_bias)
{
    int i = blockIdx.x * 256 + threadIdx.x;   // float4 index, grid sized exactly
    float4 b = bias[i];
    int4  m = mask[i];
    out_bias[i] = b;
    float4 r;
    r.x = (m.x != 0) ? b.x : -9e15f;
    r.y = (m.y != 0) ? b.y : -9e15f;
    r.z = (m.z != 0) ? b.z : -9e15f;
    r.w = (m.w != 0) ? b.w : -9e15f;
    ((float4*)g_Bm)[i] = r;
}

// ---------------- mish ------------------------------------------------------
__device__ __forceinline__ float mish_f(float x) {
    float sp = (x > 20.f) ? x : log1pf(__expf(x));
    return x * tanhf(sp);
}

// ---------------- generic NT GEMM: C = A[M,K] * B[Nn,K]^T + bias ------------
// BM=BN=64, BK=16, 256 threads, 4x4 micro-tile.
// HEADSPLIT: write C[m][nn] to Cout[h][m][d] with h=nn/64, d=nn%64.
template <int ACT, int HEADSPLIT>
__global__ void __launch_bounds__(256) gemm_nt(
    const float* __restrict__ A, const float* __restrict__ B,
    const float* __restrict__ bvec, float* __restrict__ Cout,
    int M, int Nn, int K)
{
    __shared__ float As[16][SMP];   // [k][m]
    __shared__ float Bs[16][SMP];   // [k][n]
    int t  = threadIdx.x;
    int tx = t & 15, ty = t >> 4;
    int m0 = blockIdx.y << 6, n0 = blockIdx.x << 6;
    int lr = t >> 2;              // 0..63
    int lk = (t & 3) << 2;        // 0,4,8,12

    const float* Ap = A + (size_t)(m0 + lr) * K + lk;
    const float* Bp = B + (size_t)(n0 + lr) * K + lk;

    float acc[4][4] = {};

    for (int k0 = 0; k0 < K; k0 += 16) {
        float4 a = *(const float4*)(Ap + k0);
        float4 b = *(const float4*)(Bp + k0);
        __syncthreads();
        As[lk + 0][lr] = a.x; As[lk + 1][lr] = a.y;
        As[lk + 2][lr] = a.z; As[lk + 3][lr] = a.w;
        Bs[lk + 0][lr] = b.x; Bs[lk + 1][lr] = b.y;
        Bs[lk + 2][lr] = b.z; Bs[lk + 3][lr] = b.w;
        __syncthreads();
#pragma unroll
        for (int kk = 0; kk < 16; kk++) {
            float4 av = *(const float4*)&As[kk][ty << 2];
            float4 bw = *(const float4*)&Bs[kk][tx << 2];
            acc[0][0] += av.x * bw.x; acc[0][1] += av.x * bw.y;
            acc[0][2] += av.x * bw.z; acc[0][3] += av.x * bw.w;
            acc[1][0] += av.y * bw.x; acc[1][1] += av.y * bw.y;
            acc[1][2] += av.y * bw.z; acc[1][3] += av.y * bw.w;
            acc[2][0] += av.z * bw.x; acc[2][1] += av.z * bw.y;
            acc[2][2] += av.z * bw.z; acc[2][3] += av.z * bw.w;
            acc[3][0] += av.w * bw.x; acc[3][1] += av.w * bw.y;
            acc[3][2] += av.w * bw.z; acc[3][3] += av.w * bw.w;
        }
    }

    float4 bn = *(const float4*)(bvec + n0 + (tx << 2));
#pragma unroll
    for (int i = 0; i < 4; i++) {
        int row = m0 + (ty << 2) + i;
        float4 c;
        c.x = acc[i][0] + bn.x;
        c.y = acc[i][1] + bn.y;
        c.z = acc[i][2] + bn.z;
        c.w = acc[i][3] + bn.w;
        if (ACT) {
            c.x = mish_f(c.x); c.y = mish_f(c.y);
            c.z = mish_f(c.z); c.w = mish_f(c.w);
        }
        if (HEADSPLIT) {
            // Nn tile (64 wide) is exactly one head
            float* dst = Cout + (size_t)(n0 >> 6) * (NN * HDIM)
                              + (size_t)row * HDIM + (tx << 2);
            *(float4*)dst = c;
        } else {
            *(float4*)(Cout + (size_t)row * Nn + n0 + (tx << 2)) = c;
        }
    }
}

// ---------------- flash attention with additive masked bias -----------------
// grid: (H, N/64); head fastest so 16 heads share the bias row-panel in L2.
__global__ void __launch_bounds__(256) attn_kernel()
{
    extern __shared__ float sm[];
    float* Qt = sm;                 // [d][m]  64 x SMP  (pre-scaled by 1/8)
    float* Kt = sm + 64 * SMP;      // [d][n]
    float* Vs = sm + 2 * 64 * SMP;  // [n][d]
    float* BP = sm + 3 * 64 * SMP;  // [m][n]: bias tile, then P tile (same map)

    int h  = blockIdx.x;
    int q0 = blockIdx.y << 6;
    int t  = threadIdx.x;
    int tx = t & 15, ty = t >> 4;
    int lr = t >> 2;     // 0..63 row
    int lc = t & 3;      // col group

    // load Q tile transposed, scaled by 1/sqrt(64)
    const float* Qg = g_Q + (size_t)h * (NN * HDIM) + (size_t)(q0 + lr) * HDIM;
#pragma unroll
    for (int it = 0; it < 4; it++) {
        int c = (((lc << 2) + it) << 2);       // 0..60 step 4
        float4 qv = *(const float4*)(Qg + c);
        Qt[(c + 0) * SMP + lr] = qv.x * 0.125f;
        Qt[(c + 1) * SMP + lr] = qv.y * 0.125f;
        Qt[(c + 2) * SMP + lr] = qv.z * 0.125f;
        Qt[(c + 3) * SMP + lr] = qv.w * 0.125f;
    }

    float mrow[4], lrow[4], acc[4][4] = {};
#pragma unroll
    for (int i = 0; i < 4; i++) { mrow[i] = -INFINITY; lrow[i] = 0.f; }

    for (int jb = 0; jb < NN / 64; jb++) {
        int n0 = jb << 6;
        __syncthreads();   // previous PV / loads done
        const float* Kg = g_K + (size_t)h * (NN * HDIM) + (size_t)(n0 + lr) * HDIM;
        const float* Vg = g_V + (size_t)h * (NN * HDIM) + (size_t)(n0 + lr) * HDIM;
        const float* Bg = g_Bm + (size_t)(q0 + lr) * NN + n0;
#pragma unroll
        for (int it = 0; it < 4; it++) {
            int c = (((lc << 2) + it) << 2);
            float4 kv = *(const float4*)(Kg + c);
            Kt[(c + 0) * SMP + lr] = kv.x;
            Kt[(c + 1) * SMP + lr] = kv.y;
            Kt[(c + 2) * SMP + lr] = kv.z;
            Kt[(c + 3) * SMP + lr] = kv.w;
            float4 vv = *(const float4*)(Vg + c);
            *(float4*)&Vs[lr * SMP + c] = vv;
            float4 bb = *(const float4*)(Bg + c);
            *(float4*)&BP[lr * SMP + c] = bb;
        }
        __syncthreads();

        // S = (Q/8) K^T + maskedbias
        float s[4][4];
#pragma unroll
        for (int i = 0; i < 4; i++) {
            float4 b4 = *(const float4*)&BP[((ty << 2) + i) * SMP + (tx << 2)];
            s[i][0] = b4.x; s[i][1] = b4.y; s[i][2] = b4.z; s[i][3] = b4.w;
        }
#pragma unroll 16
        for (int kk = 0; kk < 64; kk++) {
            float4 a4 = *(const float4*)&Qt[kk * SMP + (ty << 2)];
            float4 k4 = *(const float4*)&Kt[kk * SMP + (tx << 2)];
            s[0][0] += a4.x * k4.x; s[0][1] += a4.x * k4.y;
            s[0][2] += a4.x * k4.z; s[0][3] += a4.x * k4.w;
            s[1][0] += a4.y * k4.x; s[1][1] += a4.y * k4.y;
            s[1][2] += a4.y * k4.z; s[1][3] += a4.y * k4.w;
            s[2][0] += a4.z * k4.x; s[2][1] += a4.z * k4.y;
            s[2][2] += a4.z * k4.z; s[2][3] += a4.z * k4.w;
            s[3][0] += a4.w * k4.x; s[3][1] += a4.w * k4.y;
            s[3][2] += a4.w * k4.z; s[3][3] += a4.w * k4.w;
        }

        // online softmax per row; P overwrites exactly the BP entries this
        // thread read (same addresses), so no intermediate sync needed.
#pragma unroll
        for (int i = 0; i < 4; i++) {
            float mx = fmaxf(fmaxf(s[i][0], s[i][1]), fmaxf(s[i][2], s[i][3]));
#pragma unroll
            for (int off = 8; off > 0; off >>= 1)
                mx = fmaxf(mx, __shfl_xor_sync(0xffffffffu, mx, off, 16));
            float nm   = fmaxf(mrow[i], mx);
            float corr = __expf(mrow[i] - nm);
            mrow[i] = nm;
            float p0 = __expf(s[i][0] - nm);
            float p1 = __expf(s[i][1] - nm);
            float p2 = __expf(s[i][2] - nm);
            float p3 = __expf(s[i][3] - nm);
            float ps = (p0 + p1) + (p2 + p3);
#pragma unroll
            for (int off = 8; off > 0; off >>= 1)
                ps += __shfl_xor_sync(0xffffffffu, ps, off, 16);
            lrow[i] = lrow[i] * corr + ps;
            acc[i][0] *= corr; acc[i][1] *= corr;
            acc[i][2] *= corr; acc[i][3] *= corr;
            *(float4*)&BP[((ty << 2) + i) * SMP + (tx << 2)] =
                make_float4(p0, p1, p2, p3);
        }
        __syncthreads();

        // O += P V
#pragma unroll 8
        for (int nn = 0; nn < 64; nn++) {
            float4 v4 = *(const float4*)&Vs[nn * SMP + (tx << 2)];
            float pr0 = BP[((ty << 2) + 0) * SMP + nn];
            float pr1 = BP[((ty << 2) + 1) * SMP + nn];
            float pr2 = BP[((ty << 2) + 2) * SMP + nn];
            float pr3 = BP[((ty << 2) + 3) * SMP + nn];
            acc[0][0] += pr0 * v4.x; acc[0][1] += pr0 * v4.y;
            acc[0][2] += pr0 * v4.z; acc[0][3] += pr0 * v4.w;
            acc[1][0] += pr1 * v4.x; acc[1][1] += pr1 * v4.y;
            acc[1][2] += pr1 * v4.z; acc[1][3] += pr1 * v4.w;
            acc[2][0] += pr2 * v4.x; acc[2][1] += pr2 * v4.y;
            acc[2][2] += pr2 * v4.z; acc[2][3] += pr2 * v4.w;
            acc[3][0] += pr3 * v4.x; acc[3][1] += pr3 * v4.y;
            acc[3][2] += pr3 * v4.z; acc[3][3] += pr3 * v4.w;
        }
    }

    // normalize and scatter to [n][h*64+d]
#pragma unroll
    for (int i = 0; i < 4; i++) {
        float inv = 1.f / lrow[i];
        int row = q0 + (ty << 2) + i;
        float4 o = make_float4(acc[i][0] * inv, acc[i][1] * inv,
                               acc[i][2] * inv, acc[i][3] * inv);
        *(float4*)(g_vals + (size_t)row * HDT + h * HDIM + (tx << 2)) = o;
    }
}

// ---------------- launch ----------------------------------------------------
extern "C" void kernel_launch(void* const* d_in, const int* in_sizes, int n_in,
                              void* d_out, int out_size)
{
    const float* q    = (const float*)d_in[0];
    const float* k    = (const float*)d_in[1];
    const float* v    = (const float*)d_in[2];
    const float* bias = (const float*)d_in[3];
    const int*   mask = (const int*)d_in[4];
    const float* Wq   = (const float*)d_in[5];
    const float* bq   = (const float*)d_in[6];
    const float* Wk   = (const float*)d_in[7];
    const float* bk   = (const float*)d_in[8];
    const float* Wv   = (const float*)d_in[9];
    const float* bv   = (const float*)d_in[10];
    const float* Wo1  = (const float*)d_in[11];
    const float* bo1  = (const float*)d_in[12];
    const float* Wo2  = (const float*)d_in[13];
    const float* bo2  = (const float*)d_in[14];
    float* out = (float*)d_out;

    float *pQ, *pK, *pV, *pvals, *po1;
    cudaGetSymbolAddress((void**)&pQ, g_Q);
    cudaGetSymbolAddress((void**)&pK, g_K);
    cudaGetSymbolAddress((void**)&pV, g_V);
    cudaGetSymbolAddress((void**)&pvals, g_vals);
    cudaGetSymbolAddress((void**)&po1, g_o1);

    int smem = 4 * 64 * SMP * (int)sizeof(float);   // 69632 B
    cudaFuncSetAttribute(attn_kernel,
                         cudaFuncAttributeMaxDynamicSharedMemorySize, smem);

    // 1) masked bias + bias passthrough to the output tail
    prep_kernel<<<(NN * NN / 4) / 256, 256>>>(
        (const float4*)bias, (const int4*)mask,
        (float4*)(out + (size_t)NN * DIN));

    // 2) QKV projections -> [h][n][d]
    dim3 gp(HDT / 64, NN / 64);
    gemm_nt<0, 1><<<gp, 256>>>(q, Wq, bq, pQ, NN, HDT, DIN);
    gemm_nt<0, 1><<<gp, 256>>>(k, Wk, bk, pK, NN, HDT, DIN);
    gemm_nt<0, 1><<<gp, 256>>>(v, Wv, bv, pV, NN, HDT, DIN);

    // 3) attention
    attn_kernel<<<dim3(NH, NN / 64), 256, smem>>>();

    // 4) o_proj: mish(vals @ Wo1^T + bo1) @ Wo2^T + bo2
    gemm_nt<1, 0><<<dim3(HDT / 64, NN / 64), 256>>>(pvals, Wo1, bo1, po1, NN, HDT, HDT);
    gemm_nt<0, 0><<<dim3(DIN / 64, NN / 64), 256>>>(po1, Wo2, bo2, out, NN, DIN, HDT);
}

// round 12
// speedup vs baseline: 1.8961x; 1.8961x over previous
#include <cuda_runtime.h>
#include <math.h>

#define NN 3072
#define DIN 512
#define NH 16
#define HDIM 64
#define HDT 1024
#define SMP 68

#define QT 128
#define KT 64
#define KSd 68
#define VSd 72
#define PSd 68

// ---------------- scratch (device globals; no allocations allowed) ----------
__device__ float g_Q[NH * NN * HDIM];     // [h][n][d]
__device__ float g_K[NH * NN * HDIM];
__device__ float g_V[NH * NN * HDIM];
__device__ float g_Bm[(size_t)NN * NN];   // masked bias
__device__ float g_vals[NN * HDT];        // attention output [n][h*64+d]
__device__ float g_o1[NN * HDT];          // after first o_proj layer + mish

// ---------------- prep: masked bias + bias passthrough ----------------------
__global__ void __launch_bounds__(256) prep_kernel(
    const float4* __restrict__ bias, const int4* __restrict__ mask,
    float4* __restrict__ out_bias)
{
    int i = blockIdx.x * 256 + threadIdx.x;
    float4 b = bias[i];
    int4  m = mask[i];
    out_bias[i] = b;
    float4 r;
    r.x = (m.x != 0) ? b.x : -9e15f;
    r.y = (m.y != 0) ? b.y : -9e15f;
    r.z = (m.z != 0) ? b.z : -9e15f;
    r.w = (m.w != 0) ? b.w : -9e15f;
    ((float4*)g_Bm)[i] = r;
}

// ---------------- mish ------------------------------------------------------
__device__ __forceinline__ float mish_f(float x) {
    float sp = (x > 20.f) ? x : log1pf(__expf(x));
    return x * tanhf(sp);
}

// ---------------- generic NT GEMM (unchanged from passing baseline) ---------
template <int ACT, int HEADSPLIT>
__global__ void __launch_bounds__(256) gemm_nt(
    const float* __restrict__ A, const float* __restrict__ B,
    const float* __restrict__ bvec, float* __restrict__ Cout,
    int M, int Nn, int K)
{
    __shared__ float As[16][SMP];
    __shared__ float Bs[16][SMP];
    int t  = threadIdx.x;
    int tx = t & 15, ty = t >> 4;
    int m0 = blockIdx.y << 6, n0 = blockIdx.x << 6;
    int lr = t >> 2;
    int lk = (t & 3) << 2;

    const float* Ap = A + (size_t)(m0 + lr) * K + lk;
    const float* Bp = B + (size_t)(n0 + lr) * K + lk;

    float acc[4][4] = {};

    for (int k0 = 0; k0 < K; k0 += 16) {
        float4 a = *(const float4*)(Ap + k0);
        float4 b = *(const float4*)(Bp + k0);
        __syncthreads();
        As[lk + 0][lr] = a.x; As[lk + 1][lr] = a.y;
        As[lk + 2][lr] = a.z; As[lk + 3][lr] = a.w;
        Bs[lk + 0][lr] = b.x; Bs[lk + 1][lr] = b.y;
        Bs[lk + 2][lr] = b.z; Bs[lk + 3][lr] = b.w;
        __syncthreads();
#pragma unroll
        for (int kk = 0; kk < 16; kk++) {
            float4 av = *(const float4*)&As[kk][ty << 2];
            float4 bw = *(const float4*)&Bs[kk][tx << 2];
            acc[0][0] += av.x * bw.x; acc[0][1] += av.x * bw.y;
            acc[0][2] += av.x * bw.z; acc[0][3] += av.x * bw.w;
            acc[1][0] += av.y * bw.x; acc[1][1] += av.y * bw.y;
            acc[1][2] += av.y * bw.z; acc[1][3] += av.y * bw.w;
            acc[2][0] += av.z * bw.x; acc[2][1] += av.z * bw.y;
            acc[2][2] += av.z * bw.z; acc[2][3] += av.z * bw.w;
            acc[3][0] += av.w * bw.x; acc[3][1] += av.w * bw.y;
            acc[3][2] += av.w * bw.z; acc[3][3] += av.w * bw.w;
        }
    }

    float4 bn = *(const float4*)(bvec + n0 + (tx << 2));
#pragma unroll
    for (int i = 0; i < 4; i++) {
        int row = m0 + (ty << 2) + i;
        float4 c;
        c.x = acc[i][0] + bn.x;
        c.y = acc[i][1] + bn.y;
        c.z = acc[i][2] + bn.z;
        c.w = acc[i][3] + bn.w;
        if (ACT) {
            c.x = mish_f(c.x); c.y = mish_f(c.y);
            c.z = mish_f(c.z); c.w = mish_f(c.w);
        }
        if (HEADSPLIT) {
            float* dst = Cout + (size_t)(n0 >> 6) * (NN * HDIM)
                              + (size_t)row * HDIM + (tx << 2);
            *(float4*)dst = c;
        } else {
            *(float4*)(Cout + (size_t)row * Nn + n0 + (tx << 2)) = c;
        }
    }
}

// ---------------- tf32 mma helpers ------------------------------------------
__device__ __forceinline__ unsigned f2tf(float x) {
    unsigned r;
    asm("cvt.rna.tf32.f32 %0, %1;" : "=r"(r) : "f"(x));
    return r;
}

__device__ __forceinline__ void mma8(float* c, const unsigned* a,
                                     unsigned b0, unsigned b1) {
    asm volatile(
        "mma.sync.aligned.m16n8k8.row.col.f32.tf32.tf32.f32 "
        "{%0,%1,%2,%3}, {%4,%5,%6,%7}, {%8,%9}, {%0,%1,%2,%3};\n"
        : "+f"(c[0]), "+f"(c[1]), "+f"(c[2]), "+f"(c[3])
        : "r"(a[0]), "r"(a[1]), "r"(a[2]), "r"(a[3]), "r"(b0), "r"(b1));
}

// ---------------- flash attention, tf32 tensor cores ------------------------
// grid (NH, NN/QT). 8 warps, each owns m16 x n64 of the 128x64 tile, so all
// softmax row stats live inside one quad (shfl_xor 1,2 only).
__global__ void __launch_bounds__(256, 2) attn_kernel()
{
    extern __shared__ unsigned smu[];
    unsigned* Ku = smu;                   // [KT][KSd] tf32 K tile  (kv, d)
    unsigned* Vu = smu + KT * KSd;        // [KT][VSd] tf32 V tile  (kv, d)
    unsigned* Pu = Vu + KT * VSd;         // [QT][PSd] tf32 P tile  (q, kv)

    const int h    = blockIdx.x;
    const int q0   = blockIdx.y * QT;
    const int t    = threadIdx.x;
    const int wm   = t >> 5;              // warp id = m-tile
    const int lane = t & 31;
    const int qr   = lane >> 2;           // group id (rows / B-cols)
    const int ql   = lane & 3;            // thread-in-group (k cols)

    // ---- Q fragments in registers (tf32, pre-scaled by 1/sqrt(64)) ----
    unsigned qa[8][4];
    {
        const float* Q0 = g_Q + (size_t)h * (NN * HDIM)
                        + (size_t)(q0 + wm * 16 + qr) * HDIM;
        const float* Q1 = Q0 + 8 * HDIM;
#pragma unroll
        for (int ks = 0; ks < 8; ks++) {
            int cc = ks * 8 + ql;
            qa[ks][0] = f2tf(Q0[cc] * 0.125f);
            qa[ks][1] = f2tf(Q1[cc] * 0.125f);
            qa[ks][2] = f2tf(Q0[cc + 4] * 0.125f);
            qa[ks][3] = f2tf(Q1[cc + 4] * 0.125f);
        }
    }

    float o[8][4];
#pragma unroll
    for (int nt = 0; nt < 8; nt++)
        o[nt][0] = o[nt][1] = o[nt][2] = o[nt][3] = 0.f;
    float m0 = -INFINITY, m1 = -INFINITY, l0 = 0.f, l1 = 0.f;

    const int sr = t >> 2;                // staging row 0..63
    const int sc = (t & 3) * 16;          // staging col base
    const float* Kg = g_K + (size_t)h * (NN * HDIM) + (size_t)sr * HDIM + sc;
    const float* Vg = g_V + (size_t)h * (NN * HDIM) + (size_t)sr * HDIM + sc;

    for (int jb = 0; jb < NN / KT; jb++) {
        const int n0 = jb * KT;
        __syncthreads();                  // prev PV reads of Ku/Vu/Pu done
        // ---- stage K,V tiles (gmem -> smem, tf32-converted) ----
        {
            const float* kp = Kg + (size_t)n0 * HDIM;
            const float* vp = Vg + (size_t)n0 * HDIM;
#pragma unroll
            for (int i = 0; i < 4; i++) {
                float4 a = *(const float4*)(kp + i * 4);
                uint4 u;
                u.x = f2tf(a.x); u.y = f2tf(a.y); u.z = f2tf(a.z); u.w = f2tf(a.w);
                *(uint4*)&Ku[sr * KSd + sc + i * 4] = u;
                float4 b = *(const float4*)(vp + i * 4);
                uint4 w;
                w.x = f2tf(b.x); w.y = f2tf(b.y); w.z = f2tf(b.z); w.w = f2tf(b.w);
                *(uint4*)&Vu[sr * VSd + sc + i * 4] = w;
            }
        }
        // ---- masked bias -> S accumulators (direct gmem, C-frag layout) ----
        float c[8][4];
        {
            const float* B0 = g_Bm + (size_t)(q0 + wm * 16 + qr) * NN + n0 + 2 * ql;
            const float* B1 = B0 + (size_t)8 * NN;
#pragma unroll
            for (int nt = 0; nt < 8; nt++) {
                float2 x = *(const float2*)(B0 + nt * 8);
                float2 y = *(const float2*)(B1 + nt * 8);
                c[nt][0] = x.x; c[nt][1] = x.y; c[nt][2] = y.x; c[nt][3] = y.y;
            }
        }
        __syncthreads();                  // K/V tiles visible
        // ---- S = (Q/8) K^T + maskedbias ----
#pragma unroll
        for (int ks = 0; ks < 8; ks++) {
#pragma unroll
            for (int nt = 0; nt < 8; nt++) {
                unsigned b0 = Ku[(nt * 8 + qr) * KSd + ks * 8 + ql];
                unsigned b1 = Ku[(nt * 8 + qr) * KSd + ks * 8 + ql + 4];
                mma8(c[nt], qa[ks], b0, b1);
            }
        }
        // ---- online softmax (rows qr and qr+8 of this warp's m16) ----
        float t0 = -INFINITY, t1 = -INFINITY;
#pragma unroll
        for (int nt = 0; nt < 8; nt++) {
            t0 = fmaxf(t0, fmaxf(c[nt][0], c[nt][1]));
            t1 = fmaxf(t1, fmaxf(c[nt][2], c[nt][3]));
        }
        t0 = fmaxf(t0, __shfl_xor_sync(0xffffffffu, t0, 1));
        t0 = fmaxf(t0, __shfl_xor_sync(0xffffffffu, t0, 2));
        t1 = fmaxf(t1, __shfl_xor_sync(0xffffffffu, t1, 1));
        t1 = fmaxf(t1, __shfl_xor_sync(0xffffffffu, t1, 2));
        float nm0 = fmaxf(m0, t0), nm1 = fmaxf(m1, t1);
        float cor0 = __expf(m0 - nm0), cor1 = __expf(m1 - nm1);
        m0 = nm0; m1 = nm1;
        float s0 = 0.f, s1 = 0.f;
        const unsigned pr0 = (wm * 16 + qr) * PSd + 2 * ql;
        const unsigned pr1 = pr0 + 8 * PSd;
#pragma unroll
        for (int nt = 0; nt < 8; nt++) {
            float p0 = __expf(c[nt][0] - nm0);
            float p1 = __expf(c[nt][1] - nm0);
            float p2 = __expf(c[nt][2] - nm1);
            float p3 = __expf(c[nt][3] - nm1);
            s0 += p0 + p1; s1 += p2 + p3;
            uint2 u0; u0.x = f2tf(p0); u0.y = f2tf(p1);
            uint2 u1; u1.x = f2tf(p2); u1.y = f2tf(p3);
            *(uint2*)&Pu[pr0 + nt * 8] = u0;
            *(uint2*)&Pu[pr1 + nt * 8] = u1;
        }
        s0 += __shfl_xor_sync(0xffffffffu, s0, 1);
        s0 += __shfl_xor_sync(0xffffffffu, s0, 2);
        s1 += __shfl_xor_sync(0xffffffffu, s1, 1);
        s1 += __shfl_xor_sync(0xffffffffu, s1, 2);
        l0 = l0 * cor0 + s0;
        l1 = l1 * cor1 + s1;
#pragma unroll
        for (int nt = 0; nt < 8; nt++) {
            o[nt][0] *= cor0; o[nt][1] *= cor0;
            o[nt][2] *= cor1; o[nt][3] *= cor1;
        }
        __syncthreads();                  // P tile visible
        // ---- O += P V ----
#pragma unroll
        for (int ks = 0; ks < 8; ks++) {
            unsigned pa[4];
            pa[0] = Pu[(wm * 16 + qr) * PSd + ks * 8 + ql];
            pa[1] = Pu[(wm * 16 + qr + 8) * PSd + ks * 8 + ql];
            pa[2] = Pu[(wm * 16 + qr) * PSd + ks * 8 + ql + 4];
            pa[3] = Pu[(wm * 16 + qr + 8) * PSd + ks * 8 + ql + 4];
#pragma unroll
            for (int nt = 0; nt < 8; nt++) {
                unsigned b0 = Vu[(ks * 8 + ql) * VSd + nt * 8 + qr];
                unsigned b1 = Vu[(ks * 8 + ql + 4) * VSd + nt * 8 + qr];
                mma8(o[nt], pa, b0, b1);
            }
        }
    }

    // ---- normalize + scatter to [n][h*64+d] ----
    float i0 = 1.f / l0, i1 = 1.f / l1;
    float* O0 = g_vals + (size_t)(q0 + wm * 16 + qr) * HDT + h * HDIM + 2 * ql;
    float* O1 = O0 + (size_t)8 * HDT;
#pragma unroll
    for (int nt = 0; nt < 8; nt++) {
        float2 x; x.x = o[nt][0] * i0; x.y = o[nt][1] * i0;
        float2 y; y.x = o[nt][2] * i1; y.y = o[nt][3] * i1;
        *(float2*)(O0 + nt * 8) = x;
        *(float2*)(O1 + nt * 8) = y;
    }
}

// ---------------- launch ----------------------------------------------------
extern "C" void kernel_launch(void* const* d_in, const int* in_sizes, int n_in,
                              void* d_out, int out_size)
{
    const float* q    = (const float*)d_in[0];
    const float* k    = (const float*)d_in[1];
    const float* v    = (const float*)d_in[2];
    const float* bias = (const float*)d_in[3];
    const int*   mask = (const int*)d_in[4];
    const float* Wq   = (const float*)d_in[5];
    const float* bq   = (const float*)d_in[6];
    const float* Wk   = (const float*)d_in[7];
    const float* bk   = (const float*)d_in[8];
    const float* Wv   = (const float*)d_in[9];
    const float* bv   = (const float*)d_in[10];
    const float* Wo1  = (const float*)d_in[11];
    const float* bo1  = (const float*)d_in[12];
    const float* Wo2  = (const float*)d_in[13];
    const float* bo2  = (const float*)d_in[14];
    float* out = (float*)d_out;

    float *pQ, *pK, *pV, *pvals, *po1;
    cudaGetSymbolAddress((void**)&pQ, g_Q);
    cudaGetSymbolAddress((void**)&pK, g_K);
    cudaGetSymbolAddress((void**)&pV, g_V);
    cudaGetSymbolAddress((void**)&pvals, g_vals);
    cudaGetSymbolAddress((void**)&po1, g_o1);

    const int smem = (KT * KSd + KT * VSd + QT * PSd) * (int)sizeof(unsigned); // 70656
    cudaFuncSetAttribute(attn_kernel,
                         cudaFuncAttributeMaxDynamicSharedMemorySize, smem);

    // 1) masked bias + bias passthrough to the output tail
    prep_kernel<<<(NN * NN / 4) / 256, 256>>>(
        (const float4*)bias, (const int4*)mask,
        (float4*)(out + (size_t)NN * DIN));

    // 2) QKV projections -> [h][n][d]
    dim3 gp(HDT / 64, NN / 64);
    gemm_nt<0, 1><<<gp, 256>>>(q, Wq, bq, pQ, NN, HDT, DIN);
    gemm_nt<0, 1><<<gp, 256>>>(k, Wk, bk, pK, NN, HDT, DIN);
    gemm_nt<0, 1><<<gp, 256>>>(v, Wv, bv, pV, NN, HDT, DIN);

    // 3) attention (tf32 tensor cores)
    attn_kernel<<<dim3(NH, NN / QT), 256, smem>>>();

    // 4) o_proj: mish(vals @ Wo1^T + bo1) @ Wo2^T + bo2
    gemm_nt<1, 0><<<dim3(HDT / 64, NN / 64), 256>>>(pvals, Wo1, bo1, po1, NN, HDT, HDT);
    gemm_nt<0, 0><<<dim3(DIN / 64, NN / 64), 256>>>(po1, Wo2, bo2, out, NN, DIN, HDT);
}

// round 16
// speedup vs baseline: 2.2164x; 1.1689x over previous
#include <cuda_runtime.h>
#include <math.h>

#define NN 3072
#define DIN 512
#define NH 16
#define HDIM 64
#define HDT 1024

#define QT 128
#define KT 64
#define KSd 68
#define VSd 72
#define PSd 68

#define GSd 36            // gemm smem stride (36 % 32 == 4 -> conflict-free frags)

// ---------------- scratch (device globals; no allocations allowed) ----------
__device__ float g_Q[NH * NN * HDIM];     // [h][n][d]
__device__ float g_K[NH * NN * HDIM];
__device__ float g_V[NH * NN * HDIM];
__device__ float g_Bm[(size_t)NN * NN];   // masked bias
__device__ float g_vals[NN * HDT];        // attention output [n][h*64+d]
__device__ float g_o1[NN * HDT];          // after first o_proj layer + mish

// ---------------- prep: masked bias + bias passthrough ----------------------
__global__ void __launch_bounds__(256) prep_kernel(
    const float4* __restrict__ bias, const int4* __restrict__ mask,
    float4* __restrict__ out_bias)
{
    int i = blockIdx.x * 256 + threadIdx.x;
    float4 b = bias[i];
    int4  m = mask[i];
    out_bias[i] = b;
    float4 r;
    r.x = (m.x != 0) ? b.x : -9e15f;
    r.y = (m.y != 0) ? b.y : -9e15f;
    r.z = (m.z != 0) ? b.z : -9e15f;
    r.w = (m.w != 0) ? b.w : -9e15f;
    ((float4*)g_Bm)[i] = r;
}

// ---------------- mish ------------------------------------------------------
__device__ __forceinline__ float mish_f(float x) {
    float sp = (x > 20.f) ? x : log1pf(__expf(x));
    return x * tanhf(sp);
}

// ---------------- tf32 mma helpers ------------------------------------------
__device__ __forceinline__ unsigned f2tf(float x) {
    unsigned r;
    asm("cvt.rna.tf32.f32 %0, %1;" : "=r"(r) : "f"(x));
    return r;
}

__device__ __forceinline__ void hilo(float x, unsigned& h, unsigned& l) {
    h = f2tf(x);
    l = f2tf(x - __uint_as_float(h));
}

__device__ __forceinline__ void mma8(float* c, const unsigned* a,
                                     unsigned b0, unsigned b1) {
    asm volatile(
        "mma.sync.aligned.m16n8k8.row.col.f32.tf32.tf32.f32 "
        "{%0,%1,%2,%3}, {%4,%5,%6,%7}, {%8,%9}, {%0,%1,%2,%3};\n"
        : "+f"(c[0]), "+f"(c[1]), "+f"(c[2]), "+f"(c[3])
        : "r"(a[0]), "r"(a[1]), "r"(a[2]), "r"(a[3]), "r"(b0), "r"(b1));
}

// ---------------- split-tf32 NT GEMM: C = A[M,K] B[Nn,K]^T + bias -----------
// BM=128 (8 warps x m16), BN=64, k-chunk 32. 3-term split-tf32 => fp32-class
// accuracy. Fragment maps identical to the HW-validated attention kernel.
template <int ACT, int HEADSPLIT>
__global__ void __launch_bounds__(256, 2) gemm_tf32(
    const float* __restrict__ A, const float* __restrict__ B,
    const float* __restrict__ bvec, float* __restrict__ Cout,
    int M, int Nn, int K)
{
    extern __shared__ unsigned gsm[];
    unsigned* Ah = gsm;                       // [128][GSd]
    unsigned* Al = Ah + 128 * GSd;
    unsigned* Bh = Al + 128 * GSd;            // [64][GSd]
    unsigned* Bl = Bh + 64 * GSd;

    const int t    = threadIdx.x;
    const int wm   = t >> 5;
    const int lane = t & 31;
    const int qr   = lane >> 2;
    const int ql   = lane & 3;
    const int m0   = blockIdx.y << 7;
    const int n0   = blockIdx.x << 6;

    const int ar = t >> 1, ac = (t & 1) << 4;   // A: 2 thr/row, 16 floats each
    const int br = t >> 2, bc = (t & 3) << 3;   // B: 4 thr/row, 8 floats each

    const float* Ap = A + (size_t)(m0 + ar) * K + ac;
    const float* Bp = B + (size_t)(n0 + br) * K + bc;

    float acc[8][4];
#pragma unroll
    for (int nt = 0; nt < 8; nt++)
        acc[nt][0] = acc[nt][1] = acc[nt][2] = acc[nt][3] = 0.f;

    for (int k0 = 0; k0 < K; k0 += 32) {
        __syncthreads();
        // ---- stage A chunk (hi/lo) ----
#pragma unroll
        for (int i = 0; i < 4; i++) {
            float4 a = *(const float4*)(Ap + k0 + i * 4);
            uint4 h, l;
            hilo(a.x, h.x, l.x); hilo(a.y, h.y, l.y);
            hilo(a.z, h.z, l.z); hilo(a.w, h.w, l.w);
            *(uint4*)&Ah[ar * GSd + ac + i * 4] = h;
            *(uint4*)&Al[ar * GSd + ac + i * 4] = l;
        }
        // ---- stage B chunk (hi/lo) ----
#pragma unroll
        for (int i = 0; i < 2; i++) {
            float4 b = *(const float4*)(Bp + k0 + i * 4);
            uint4 h, l;
            hilo(b.x, h.x, l.x); hilo(b.y, h.y, l.y);
            hilo(b.z, h.z, l.z); hilo(b.w, h.w, l.w);
            *(uint4*)&Bh[br * GSd + bc + i * 4] = h;
            *(uint4*)&Bl[br * GSd + bc + i * 4] = l;
        }
        __syncthreads();
#pragma unroll
        for (int k8 = 0; k8 < 4; k8++) {
            const int arow = (wm * 16 + qr) * GSd + k8 * 8 + ql;
            unsigned pah[4], pal[4];
            pah[0] = Ah[arow];            pah[1] = Ah[arow + 8 * GSd];
            pah[2] = Ah[arow + 4];        pah[3] = Ah[arow + 8 * GSd + 4];
            pal[0] = Al[arow];            pal[1] = Al[arow + 8 * GSd];
            pal[2] = Al[arow + 4];        pal[3] = Al[arow + 8 * GSd + 4];
#pragma unroll
            for (int nt = 0; nt < 8; nt++) {
                const int brow = (nt * 8 + qr) * GSd + k8 * 8 + ql;
                unsigned bh0 = Bh[brow], bh1 = Bh[brow + 4];
                unsigned bl0 = Bl[brow], bl1 = Bl[brow + 4];
                mma8(acc[nt], pah, bh0, bh1);
                mma8(acc[nt], pah, bl0, bl1);
                mma8(acc[nt], pal, bh0, bh1);
            }
        }
    }

    // ---- epilogue: bias, activation, scatter (C-frag layout) ----
    const int row0 = m0 + wm * 16 + qr;
#pragma unroll
    for (int nt = 0; nt < 8; nt++) {
        float2 bn = *(const float2*)(bvec + n0 + nt * 8 + 2 * ql);
        float c0 = acc[nt][0] + bn.x;
        float c1 = acc[nt][1] + bn.y;
        float c2 = acc[nt][2] + bn.x;
        float c3 = acc[nt][3] + bn.y;
        if (ACT) {
            c0 = mish_f(c0); c1 = mish_f(c1);
            c2 = mish_f(c2); c3 = mish_f(c3);
        }
        if (HEADSPLIT) {
            float* d0 = Cout + (size_t)(n0 >> 6) * (NN * HDIM)
                             + (size_t)row0 * HDIM + nt * 8 + 2 * ql;
            float2 x; x.x = c0; x.y = c1;
            float2 y; y.x = c2; y.y = c3;
            *(float2*)d0 = x;
            *(float2*)(d0 + (size_t)8 * HDIM) = y;
        } else {
            float* d0 = Cout + (size_t)row0 * Nn + n0 + nt * 8 + 2 * ql;
            float2 x; x.x = c0; x.y = c1;
            float2 y; y.x = c2; y.y = c3;
            *(float2*)d0 = x;
            *(float2*)(d0 + (size_t)8 * Nn) = y;
        }
    }
}

// ---------------- flash attention, tf32 tensor cores (R12-validated) --------
__global__ void __launch_bounds__(256, 2) attn_kernel()
{
    extern __shared__ unsigned smu[];
    unsigned* Ku = smu;                   // [KT][KSd] tf32 K tile  (kv, d)
    unsigned* Vu = smu + KT * KSd;        // [KT][VSd] tf32 V tile  (kv, d)
    unsigned* Pu = Vu + KT * VSd;         // [QT][PSd] tf32 P tile  (q, kv)

    const int h    = blockIdx.x;
    const int q0   = blockIdx.y * QT;
    const int t    = threadIdx.x;
    const int wm   = t >> 5;
    const int lane = t & 31;
    const int qr   = lane >> 2;
    const int ql   = lane & 3;

    unsigned qa[8][4];
    {
        const float* Q0 = g_Q + (size_t)h * (NN * HDIM)
                        + (size_t)(q0 + wm * 16 + qr) * HDIM;
        const float* Q1 = Q0 + 8 * HDIM;
#pragma unroll
        for (int ks = 0; ks < 8; ks++) {
            int cc = ks * 8 + ql;
            qa[ks][0] = f2tf(Q0[cc] * 0.125f);
            qa[ks][1] = f2tf(Q1[cc] * 0.125f);
            qa[ks][2] = f2tf(Q0[cc + 4] * 0.125f);
            qa[ks][3] = f2tf(Q1[cc + 4] * 0.125f);
        }
    }

    float o[8][4];
#pragma unroll
    for (int nt = 0; nt < 8; nt++)
        o[nt][0] = o[nt][1] = o[nt][2] = o[nt][3] = 0.f;
    float m0 = -INFINITY, m1 = -INFINITY, l0 = 0.f, l1 = 0.f;

    const int sr = t >> 2;
    const int sc = (t & 3) * 16;
    const float* Kg = g_K + (size_t)h * (NN * HDIM) + (size_t)sr * HDIM + sc;
    const float* Vg = g_V + (size_t)h * (NN * HDIM) + (size_t)sr * HDIM + sc;

    for (int jb = 0; jb < NN / KT; jb++) {
        const int n0 = jb * KT;
        __syncthreads();
        {
            const float* kp = Kg + (size_t)n0 * HDIM;
            const float* vp = Vg + (size_t)n0 * HDIM;
#pragma unroll
            for (int i = 0; i < 4; i++) {
                float4 a = *(const float4*)(kp + i * 4);
                uint4 u;
                u.x = f2tf(a.x); u.y = f2tf(a.y); u.z = f2tf(a.z); u.w = f2tf(a.w);
                *(uint4*)&Ku[sr * KSd + sc + i * 4] = u;
                float4 b = *(const float4*)(vp + i * 4);
                uint4 w;
                w.x = f2tf(b.x); w.y = f2tf(b.y); w.z = f2tf(b.z); w.w = f2tf(b.w);
                *(uint4*)&Vu[sr * VSd + sc + i * 4] = w;
            }
        }
        float c[8][4];
        {
            const float* B0 = g_Bm + (size_t)(q0 + wm * 16 + qr) * NN + n0 + 2 * ql;
            const float* B1 = B0 + (size_t)8 * NN;
#pragma unroll
            for (int nt = 0; nt < 8; nt++) {
                float2 x = *(const float2*)(B0 + nt * 8);
                float2 y = *(const float2*)(B1 + nt * 8);
                c[nt][0] = x.x; c[nt][1] = x.y; c[nt][2] = y.x; c[nt][3] = y.y;
            }
        }
        __syncthreads();
#pragma unroll
        for (int ks = 0; ks < 8; ks++) {
#pragma unroll
            for (int nt = 0; nt < 8; nt++) {
                unsigned b0 = Ku[(nt * 8 + qr) * KSd + ks * 8 + ql];
                unsigned b1 = Ku[(nt * 8 + qr) * KSd + ks * 8 + ql + 4];
                mma8(c[nt], qa[ks], b0, b1);
            }
        }
        float t0 = -INFINITY, t1 = -INFINITY;
#pragma unroll
        for (int nt = 0; nt < 8; nt++) {
            t0 = fmaxf(t0, fmaxf(c[nt][0], c[nt][1]));
            t1 = fmaxf(t1, fmaxf(c[nt][2], c[nt][3]));
        }
        t0 = fmaxf(t0, __shfl_xor_sync(0xffffffffu, t0, 1));
        t0 = fmaxf(t0, __shfl_xor_sync(0xffffffffu, t0, 2));
        t1 = fmaxf(t1, __shfl_xor_sync(0xffffffffu, t1, 1));
        t1 = fmaxf(t1, __shfl_xor_sync(0xffffffffu, t1, 2));
        float nm0 = fmaxf(m0, t0), nm1 = fmaxf(m1, t1);
        float cor0 = __expf(m0 - nm0), cor1 = __expf(m1 - nm1);
        m0 = nm0; m1 = nm1;
        float s0 = 0.f, s1 = 0.f;
        const unsigned pr0 = (wm * 16 + qr) * PSd + 2 * ql;
        const unsigned pr1 = pr0 + 8 * PSd;
#pragma unroll
        for (int nt = 0; nt < 8; nt++) {
            float p0 = __expf(c[nt][0] - nm0);
            float p1 = __expf(c[nt][1] - nm0);
            float p2 = __expf(c[nt][2] - nm1);
            float p3 = __expf(c[nt][3] - nm1);
            s0 += p0 + p1; s1 += p2 + p3;
            uint2 u0; u0.x = f2tf(p0); u0.y = f2tf(p1);
            uint2 u1; u1.x = f2tf(p2); u1.y = f2tf(p3);
            *(uint2*)&Pu[pr0 + nt * 8] = u0;
            *(uint2*)&Pu[pr1 + nt * 8] = u1;
        }
        s0 += __shfl_xor_sync(0xffffffffu, s0, 1);
        s0 += __shfl_xor_sync(0xffffffffu, s0, 2);
        s1 += __shfl_xor_sync(0xffffffffu, s1, 1);
        s1 += __shfl_xor_sync(0xffffffffu, s1, 2);
        l0 = l0 * cor0 + s0;
        l1 = l1 * cor1 + s1;
#pragma unroll
        for (int nt = 0; nt < 8; nt++) {
            o[nt][0] *= cor0; o[nt][1] *= cor0;
            o[nt][2] *= cor1; o[nt][3] *= cor1;
        }
        __syncthreads();
#pragma unroll
        for (int ks = 0; ks < 8; ks++) {
            unsigned pa[4];
            pa[0] = Pu[(wm * 16 + qr) * PSd + ks * 8 + ql];
            pa[1] = Pu[(wm * 16 + qr + 8) * PSd + ks * 8 + ql];
            pa[2] = Pu[(wm * 16 + qr) * PSd + ks * 8 + ql + 4];
            pa[3] = Pu[(wm * 16 + qr + 8) * PSd + ks * 8 + ql + 4];
#pragma unroll
            for (int nt = 0; nt < 8; nt++) {
                unsigned b0 = Vu[(ks * 8 + ql) * VSd + nt * 8 + qr];
                unsigned b1 = Vu[(ks * 8 + ql + 4) * VSd + nt * 8 + qr];
                mma8(o[nt], pa, b0, b1);
            }
        }
    }

    float i0 = 1.f / l0, i1 = 1.f / l1;
    float* O0 = g_vals + (size_t)(q0 + wm * 16 + qr) * HDT + h * HDIM + 2 * ql;
    float* O1 = O0 + (size_t)8 * HDT;
#pragma unroll
    for (int nt = 0; nt < 8; nt++) {
        float2 x; x.x = o[nt][0] * i0; x.y = o[nt][1] * i0;
        float2 y; y.x = o[nt][2] * i1; y.y = o[nt][3] * i1;
        *(float2*)(O0 + nt * 8) = x;
        *(float2*)(O1 + nt * 8) = y;
    }
}

// ---------------- launch ----------------------------------------------------
extern "C" void kernel_launch(void* const* d_in, const int* in_sizes, int n_in,
                              void* d_out, int out_size)
{
    const float* q    = (const float*)d_in[0];
    const float* k    = (const float*)d_in[1];
    const float* v    = (const float*)d_in[2];
    const float* bias = (const float*)d_in[3];
    const int*   mask = (const int*)d_in[4];
    const float* Wq   = (const float*)d_in[5];
    const float* bq   = (const float*)d_in[6];
    const float* Wk   = (const float*)d_in[7];
    const float* bk   = (const float*)d_in[8];
    const float* Wv   = (const float*)d_in[9];
    const float* bv   = (const float*)d_in[10];
    const float* Wo1  = (const float*)d_in[11];
    const float* bo1  = (const float*)d_in[12];
    const float* Wo2  = (const float*)d_in[13];
    const float* bo2  = (const float*)d_in[14];
    float* out = (float*)d_out;

    float *pQ, *pK, *pV, *pvals, *po1;
    cudaGetSymbolAddress((void**)&pQ, g_Q);
    cudaGetSymbolAddress((void**)&pK, g_K);
    cudaGetSymbolAddress((void**)&pV, g_V);
    cudaGetSymbolAddress((void**)&pvals, g_vals);
    cudaGetSymbolAddress((void**)&po1, g_o1);

    const int asmem = (KT * KSd + KT * VSd + QT * PSd) * (int)sizeof(unsigned); // 70656
    cudaFuncSetAttribute(attn_kernel,
                         cudaFuncAttributeMaxDynamicSharedMemorySize, asmem);
    const int gsmem = (2 * 128 * GSd + 2 * 64 * GSd) * (int)sizeof(unsigned);   // 55296
    cudaFuncSetAttribute(gemm_tf32<0, 1>,
                         cudaFuncAttributeMaxDynamicSharedMemorySize, gsmem);
    cudaFuncSetAttribute(gemm_tf32<1, 0>,
                         cudaFuncAttributeMaxDynamicSharedMemorySize, gsmem);
    cudaFuncSetAttribute(gemm_tf32<0, 0>,
                         cudaFuncAttributeMaxDynamicSharedMemorySize, gsmem);

    // 1) masked bias + bias passthrough to the output tail
    prep_kernel<<<(NN * NN / 4) / 256, 256>>>(
        (const float4*)bias, (const int4*)mask,
        (float4*)(out + (size_t)NN * DIN));

    // 2) QKV projections -> [h][n][d]  (split-tf32 tensor cores)
    dim3 gp(HDT / 64, NN / 128);
    gemm_tf32<0, 1><<<gp, 256, gsmem>>>(q, Wq, bq, pQ, NN, HDT, DIN);
    gemm_tf32<0, 1><<<gp, 256, gsmem>>>(k, Wk, bk, pK, NN, HDT, DIN);
    gemm_tf32<0, 1><<<gp, 256, gsmem>>>(v, Wv, bv, pV, NN, HDT, DIN);

    // 3) attention (tf32 tensor cores)
    attn_kernel<<<dim3(NH, NN / QT), 256, asmem>>>();

    // 4) o_proj: mish(vals @ Wo1^T + bo1) @ Wo2^T + bo2  (split-tf32)
    gemm_tf32<1, 0><<<dim3(HDT / 64, NN / 128), 256, gsmem>>>(pvals, Wo1, bo1, po1, NN, HDT, HDT);
    gemm_tf32<0, 0><<<dim3(DIN / 64, NN / 128), 256, gsmem>>>(po1, Wo2, bo2, out, NN, DIN, HDT);
}